// round 17
// baseline (speedup 1.0000x reference)
#include <cuda_runtime.h>
#include <cuda_fp16.h>
#include <math.h>
#include <stdint.h>
#include <stddef.h>

#define B_ 16
#define C_ 512
#define N_ 4096
#define NROWS (B_*C_)

#define TM 128
#define TN 128
#define NTHREADS 128

#define A_PAD 40
#define B_PAD_T 136
#define TILEA_H 5120
#define TILEB_H 4352
#define TILEA_BYTES 10240
#define TILEB_BYTES 8704

#define AH_BYTES 10240
#define STG_BYTES 20480
#define NSTAGE 5
#define SMEM_TILES 1024
#define SMEM_TOTAL (SMEM_TILES + NSTAGE*STG_BYTES)   // 103424, 2 CTAs/SM

// batch strides (halves)
#define BMN_B    ((size_t)32*16*TILEB_H)
#define AFMT_BIG ((size_t)4*128*TILEA_H)
#define AFMT_AT  ((size_t)4*16*TILEA_H)
#define RM_B     ((size_t)C_*N_)

// ---------------- scratch ----------------
__device__ __half g_vhT [(size_t)B_*BMN_B];
__device__ __half g_xhT [(size_t)B_*BMN_B];
__device__ __half g_yhT [(size_t)B_*BMN_B];
__device__ __half g_sq  [(size_t)B_*AFMT_BIG];
__device__ __half g_kh  [(size_t)B_*AFMT_BIG];
__device__ __half g_qh  [(size_t)B_*AFMT_BIG];
__device__ __half g_at  [(size_t)B_*AFMT_AT];
__device__ __half g_gph [(size_t)B_*RM_B];
__device__ __half g_wcomb[20*16*TILEA_H];   // combined interleaved weights (2560 rows)
__device__ __half g_wmA  [ 8*16*TILEA_H];   // Wm A-fmt (for W' GEMM)
__device__ __half g_wvT  [ 4*16*TILEB_H];   // Wv MN-512 tiles (B of W' GEMM)
__device__ __half g_wgT  [ 4*32*TILEA_H];
__device__ __half g_wrT  [ 4*16*TILEA_H];
__device__ float  g_bcomb[2560];

// ---------------- PTX helpers ----------------
__device__ __forceinline__ uint32_t smem_u32(const void* p){
    uint32_t a;
    asm("{ .reg .u64 t; cvta.to.shared.u64 t, %1; cvt.u32.u64 %0, t; }"
        : "=r"(a) : "l"(p));
    return a;
}
__device__ __forceinline__ void bulk_g2s(uint32_t dst, const void* src,
                                         uint32_t bytes, uint32_t bar){
    asm volatile(
        "cp.async.bulk.shared::cta.global.mbarrier::complete_tx::bytes "
        "[%0], [%1], %2, [%3];"
        :: "r"(dst), "l"(src), "r"(bytes), "r"(bar) : "memory");
}
__device__ __forceinline__ void mbar_init(uint32_t a, uint32_t n){
    asm volatile("mbarrier.init.shared.b64 [%0], %1;" :: "r"(a), "r"(n) : "memory");
}
__device__ __forceinline__ void mbar_expect(uint32_t a, uint32_t bytes){
    asm volatile("mbarrier.arrive.expect_tx.shared.b64 _, [%0], %1;"
                 :: "r"(a), "r"(bytes) : "memory");
}
__device__ __forceinline__ void mbar_wait(uint32_t a, uint32_t parity){
    asm volatile(
        "{\n\t.reg .pred P;\n\tWAITL%=:\n\t"
        "mbarrier.try_wait.parity.shared.b64 P, [%0], %1;\n\t"
        "@!P bra WAITL%=;\n\t}"
        :: "r"(a), "r"(parity) : "memory");
}
__device__ __forceinline__ void ldsm4(uint32_t* r, uint32_t addr){
    asm volatile("ldmatrix.sync.aligned.m8n8.x4.shared.b16 {%0,%1,%2,%3}, [%4];"
        : "=r"(r[0]), "=r"(r[1]), "=r"(r[2]), "=r"(r[3]) : "r"(addr));
}
__device__ __forceinline__ void ldsm4t(uint32_t* r, uint32_t addr){
    asm volatile("ldmatrix.sync.aligned.m8n8.x4.trans.shared.b16 {%0,%1,%2,%3}, [%4];"
        : "=r"(r[0]), "=r"(r[1]), "=r"(r[2]), "=r"(r[3]) : "r"(addr));
}
__device__ __forceinline__ void mma16816(float* c, const uint32_t* a, const uint32_t* b){
    asm volatile(
        "mma.sync.aligned.m16n8k16.row.col.f32.f16.f16.f32 "
        "{%0,%1,%2,%3}, {%4,%5,%6,%7}, {%8,%9}, {%0,%1,%2,%3};"
        : "+f"(c[0]), "+f"(c[1]), "+f"(c[2]), "+f"(c[3])
        : "r"(a[0]), "r"(a[1]), "r"(a[2]), "r"(a[3]), "r"(b[0]), "r"(b[1]));
}
__device__ __forceinline__ uint32_t pack_h2(float x, float y){
    __half2 p(__float2half_rn(x), __float2half_rn(y));
    return *(uint32_t*)&p;
}
__device__ __forceinline__ float2 unpack_h2(uint32_t u){
    __half2 p = *(__half2*)&u;
    return make_float2(__half2float(p.x), __half2float(p.y));
}

// ---------------------------------------------------------------------------
// fp16 GEMM, bulk-copy pipeline (5 stages). CTA 128x128, 4 warps, 64x64 tiles.
// modes: 0 scores / 1 final / 4 y / 5 gate / 6 W'->combined / 7 merged qkv+mqk
// ---------------------------------------------------------------------------
__global__ void __launch_bounds__(NTHREADS, 2) mma_gemm(
    const __half* __restrict__ A, int aNC, size_t aTB,
    const __half* __restrict__ B1, int b1NC, size_t b1TB,
    const __half* __restrict__ B2, int b2NC, size_t b2TB, int K1c,
    const float* __restrict__ bias, float scale,
    float* __restrict__ Y32,
    __half* __restrict__ O1, __half* __restrict__ O2,
    const __half* __restrict__ E1, const __half* __restrict__ E2,
    int NC, int transB, int mode)
{
    extern __shared__ char smem[];
    const uint32_t sbase = smem_u32(smem);
    const uint32_t tiles = sbase + SMEM_TILES;

    const int tid  = threadIdx.x;
    const int lane = tid & 31;
    const int wid  = tid >> 5;
    const int wm   = wid & 1;
    const int wn   = wid >> 1;
    const int b    = blockIdx.z;
    const int m0   = blockIdx.y * TM;
    const int n0   = blockIdx.x * TN;

    const __half* Ab  = A  + (size_t)b * aTB;
    const __half* B1b = B1 + (size_t)b * b1TB;
    const __half* B2b = B2 ? (B2 + (size_t)b * b2TB) : (const __half*)0;

    const uint32_t expect = TILEA_BYTES + (transB ? TILEB_BYTES : TILEA_BYTES);

    if (tid == 0){
        #pragma unroll
        for (int s = 0; s < NSTAGE; s++) mbar_init(sbase + s*8, 1);
    }

    auto issue = [&](int kc){
        const int s = kc % NSTAGE;
        const uint32_t bar = sbase + s*8;
        mbar_expect(bar, expect);
        const __half* srcA = Ab + ((size_t)(m0 >> 7) * aNC + kc) * TILEA_H;
        bulk_g2s(tiles + s*STG_BYTES, srcA, TILEA_BYTES, bar);
        if (transB){
            const __half* srcB = (kc < K1c)
                ? B1b + ((size_t)(n0 >> 7) * b1NC + kc) * TILEB_H
                : B2b + ((size_t)(n0 >> 7) * b2NC + (kc - K1c)) * TILEB_H;
            bulk_g2s(tiles + s*STG_BYTES + AH_BYTES, srcB, TILEB_BYTES, bar);
        } else {
            const __half* srcB = B1b + ((size_t)(n0 >> 7) * b1NC + kc) * TILEA_H;
            bulk_g2s(tiles + s*STG_BYTES + AH_BYTES, srcB, TILEA_BYTES, bar);
        }
    };

    if (tid == 0){
        issue(0);
        if (NC > 1) issue(1);
        if (NC > 2) issue(2);
        if (NC > 3) issue(3);
    }
    __syncthreads();

    float acc[4][8][4];
    #pragma unroll
    for (int i = 0; i < 4; i++)
        #pragma unroll
        for (int j = 0; j < 8; j++)
            #pragma unroll
            for (int r = 0; r < 4; r++) acc[i][j][r] = 0.f;

    const int a_lrow = lane & 15;
    const int a_lcol = (lane >> 4) << 3;
    const int i4 = lane >> 3;
    const int r8 = lane & 7;
    const int kt = lane & 15;
    const int nh = lane >> 4;

    int st = 0, pa = 0;
    for (int kc = 0; kc < NC; kc++){
        mbar_wait(sbase + st*8, pa);
        __syncthreads();

        const uint32_t sa = tiles + st * STG_BYTES;
        const uint32_t sb = sa + AH_BYTES;

        uint32_t ah[2][4][4], bb[2][8][2];
        #pragma unroll
        for (int ks = 0; ks < 2; ks++){
            #pragma unroll
            for (int mt = 0; mt < 4; mt++){
                uint32_t ad = sa + 2 * ((wm*64 + mt*16 + a_lrow) * A_PAD + ks*16 + a_lcol);
                ldsm4(ah[ks][mt], ad);
            }
            #pragma unroll
            for (int p = 0; p < 4; p++){
                uint32_t r4[4];
                if (transB){
                    uint32_t bd = sb + 2 * ((ks*16 + kt) * B_PAD_T + wn*64 + (2*p + nh)*8);
                    ldsm4t(r4, bd);
                } else {
                    int row = wn*64 + (2*p + (i4 >> 1))*8 + r8;
                    int col = ks*16 + (i4 & 1)*8;
                    ldsm4(r4, sb + 2 * (row * A_PAD + col));
                }
                bb[ks][2*p][0]   = r4[0];
                bb[ks][2*p][1]   = r4[1];
                bb[ks][2*p+1][0] = r4[2];
                bb[ks][2*p+1][1] = r4[3];
            }
        }

        if (tid == 0 && kc + 4 < NC) issue(kc + 4);

        #pragma unroll
        for (int ks = 0; ks < 2; ks++)
            #pragma unroll
            for (int mt = 0; mt < 4; mt++)
                #pragma unroll
                for (int nt = 0; nt < 8; nt++)
                    mma16816(acc[mt][nt], ah[ks][mt], bb[ks][nt]);

        if (++st == NSTAGE){ st = 0; pa ^= 1; }
    }

    // ---- epilogue ----
    const int g = lane >> 2;
    const int t = lane & 3;
    #pragma unroll
    for (int mt = 0; mt < 4; mt++){
        int m = m0 + wm*64 + mt*16 + g;
        float bi_lo = bias ? bias[m]     : 0.f;
        float bi_hi = bias ? bias[m + 8] : 0.f;
        #pragma unroll
        for (int nt = 0; nt < 8; nt++){
            int nn = n0 + wn*64 + nt*8 + 2*t;
            float v00 = acc[mt][nt][0] * scale + bi_lo;
            float v01 = acc[mt][nt][1] * scale + bi_lo;
            float v10 = acc[mt][nt][2] * scale + bi_hi;
            float v11 = acc[mt][nt][3] * scale + bi_hi;

            if (mode == 0){
                size_t off0 = (size_t)b*((size_t)C_*C_) + (size_t)m*C_ + nn;
                size_t off1 = off0 + (size_t)8*C_;
                float2 o0 = {v00, v01}, o1 = {v10, v11};
                *(float2*)(Y32 + off0) = o0;
                *(float2*)(Y32 + off1) = o1;
            } else if (mode == 7){
                if (m0 < 2048){
                    // paired region: even rows = qk, odd rows = m-values
                    float sgn  = (m0 < 1024) ? -1.f : 1.f;
                    int   base = (m0 < 1024) ? 0 : 1024;
                    __half* dst = (m0 < 1024) ? O1 : O2;
                    float w00 = __shfl_xor_sync(0xffffffffu, v00, 4);
                    float w01 = __shfl_xor_sync(0xffffffffu, v01, 4);
                    float w10 = __shfl_xor_sync(0xffffffffu, v10, 4);
                    float w11 = __shfl_xor_sync(0xffffffffu, v11, 4);
                    if ((g & 1) == 0){
                        int c0 = (m - base) >> 1;
                        int c1 = c0 + 4;
                        float t00 = fmaxf(v00*w00, 0.f) * sgn;
                        float t01 = fmaxf(v01*w01, 0.f) * sgn;
                        float t10 = fmaxf(v10*w10, 0.f) * sgn;
                        float t11 = fmaxf(v11*w11, 0.f) * sgn;
                        size_t a0 = (size_t)b*AFMT_BIG
                            + ((size_t)(c0>>7)*128 + (nn>>5))*TILEA_H
                            + (size_t)(c0&127)*A_PAD + (nn&31);
                        size_t a1 = (size_t)b*AFMT_BIG
                            + ((size_t)(c1>>7)*128 + (nn>>5))*TILEA_H
                            + (size_t)(c1&127)*A_PAD + (nn&31);
                        *(uint32_t*)(dst + a0) = pack_h2(t00, t01);
                        *(uint32_t*)(dst + a1) = pack_h2(t10, t11);
                    }
                } else {
                    // v rows -> MN tiles (vout passed via Y32)
                    __half* vout = (__half*)Y32;
                    int c = m - 2048;
                    size_t bt = (size_t)b*BMN_B
                        + ((size_t)(nn>>7)*16 + (c>>5))*TILEB_H + (nn & 127);
                    *(uint32_t*)(vout + bt + (size_t)(c & 31)*B_PAD_T)       = pack_h2(v00, v01);
                    *(uint32_t*)(vout + bt + (size_t)((c & 31) + 8)*B_PAD_T) = pack_h2(v10, v11);
                }
            } else if (mode == 6){
                // W' -> combined tiles, odd interleaved rows
                int base_r = (m < 512) ? 0 : 1024;
                int mrel   = (m < 512) ? m : m - 512;
                int R0 = base_r + 2*mrel + 1;
                int R1 = R0 + 16;
                size_t a0 = ((size_t)(R0>>7)*16 + (nn>>5))*TILEA_H
                          + (size_t)(R0&127)*A_PAD + (nn&31);
                size_t a1 = ((size_t)(R1>>7)*16 + (nn>>5))*TILEA_H
                          + (size_t)(R1&127)*A_PAD + (nn&31);
                *(uint32_t*)(O1 + a0) = pack_h2(v00, v01);
                *(uint32_t*)(O1 + a1) = pack_h2(v10, v11);
            } else if (mode == 4){
                size_t bt = (size_t)b*BMN_B
                    + ((size_t)(nn>>7)*16 + (m>>5))*TILEB_H + (nn & 127);
                *(uint32_t*)(O1 + bt + (size_t)(m & 31)*B_PAD_T)       = pack_h2(v00, v01);
                *(uint32_t*)(O1 + bt + (size_t)((m & 31) + 8)*B_PAD_T) = pack_h2(v10, v11);
            } else if (mode == 5){
                size_t o0 = (size_t)b*RM_B + (size_t)m*N_ + nn;
                *(uint32_t*)(O1 + o0)                = pack_h2(v00, v01);
                *(uint32_t*)(O1 + o0 + 8*(size_t)N_) = pack_h2(v10, v11);
            } else { // mode 1
                size_t eo0 = (size_t)b*RM_B + (size_t)m*N_ + nn;
                size_t eo1 = eo0 + 8*(size_t)N_;
                float2 gp0 = unpack_h2(*(const uint32_t*)(E1 + eo0));
                float2 gp1 = unpack_h2(*(const uint32_t*)(E1 + eo1));
                size_t yt = (size_t)b*BMN_B
                    + ((size_t)(nn>>7)*16 + (m>>5))*TILEB_H + (nn & 127);
                float2 y0 = unpack_h2(*(const uint32_t*)(E2 + yt + (size_t)(m & 31)*B_PAD_T));
                float2 y1 = unpack_h2(*(const uint32_t*)(E2 + yt + (size_t)((m & 31) + 8)*B_PAD_T));
                float s0 = 1.f/(1.f+__expf(-gp0.x));
                float s1 = 1.f/(1.f+__expf(-gp0.y));
                float s2 = 1.f/(1.f+__expf(-gp1.x));
                float s3 = 1.f/(1.f+__expf(-gp1.y));
                size_t off0 = (size_t)b*RM_B + (size_t)m*N_ + nn;
                size_t off1 = off0 + 8*(size_t)N_;
                float2 o0, o1;
                o0.x = y0.x + s0*(v00 - y0.x);
                o0.y = y0.y + s1*(v01 - y0.y);
                o1.x = y1.x + s2*(v10 - y1.x);
                o1.y = y1.y + s3*(v11 - y1.y);
                *(float2*)(Y32 + off0) = o0;
                *(float2*)(Y32 + off1) = o1;
            }
        }
    }
}

// ---------------------------------------------------------------------------
// Fused retile: Wqkv->combined(even/interleaved rows), Wm->A-fmt, Wv->MN512,
// Wg->A-fmt, Wr->A-fmt, x->MN tiles.
#define RW0 (3*C_*C_)     // Wqkv
#define RW1 (2*C_*C_)     // Wm
#define RW2 (C_*C_)       // Wv (slice of Wqkv)
#define RW3 (2*C_*C_)     // Wg
#define RW4 (C_*C_)       // Wr
#define RX  (B_*C_*N_)
#define RT_TOTAL (RW0+RW1+RW2+RW3+RW4+RX)

__global__ void retile_all(
    const float* __restrict__ wqkv, __half* __restrict__ dcomb,
    const float* __restrict__ wm,   __half* __restrict__ dmA,
    __half* __restrict__ dvT,
    const float* __restrict__ wg,   __half* __restrict__ dgT,
    const float* __restrict__ wr,   __half* __restrict__ drT,
    const float* __restrict__ x,    __half* __restrict__ dx)
{
    int i = blockIdx.x * 256 + threadIdx.x;
    if (i >= RT_TOTAL) return;
    if (i < RW0){
        // Wqkv row m, col k -> combined row R(m)
        int m = i / C_, k = i % C_;
        int R = (m < 512) ? 2*m : ((m < 1024) ? 1024 + 2*(m - 512) : 2048 + (m - 1024));
        size_t o = ((size_t)(R>>7)*16 + (k>>5))*TILEA_H
                 + (size_t)(R & 127)*A_PAD + (k & 31);
        dcomb[o] = __float2half_rn(wqkv[i]);
    } else if (i < RW0+RW1){
        int off = i - RW0;
        int m = off / C_, k = off % C_;
        size_t o = ((size_t)(m>>7)*16 + (k>>5))*TILEA_H
                 + (size_t)(m & 127)*A_PAD + (k & 31);
        dmA[o] = __float2half_rn(wm[off]);
    } else if (i < RW0+RW1+RW2){
        int off = i - RW0 - RW1;           // Wv element (c, k')
        int c = off >> 9, kp = off & 511;
        size_t o = ((size_t)(kp>>7)*16 + (c>>5))*TILEB_H
                 + (size_t)(c & 31)*B_PAD_T + (kp & 127);
        dvT[o] = __float2half_rn(wqkv[(size_t)(1024 + c)*C_ + kp]);
    } else if (i < RW0+RW1+RW2+RW3){
        int off = i - RW0 - RW1 - RW2;
        int m = off / (2*C_), k = off % (2*C_);
        size_t o = ((size_t)(m>>7)*32 + (k>>5))*TILEA_H
                 + (size_t)(m & 127)*A_PAD + (k & 31);
        dgT[o] = __float2half_rn(wg[off]);
    } else if (i < RW0+RW1+RW2+RW3+RW4){
        int off = i - RW0 - RW1 - RW2 - RW3;
        int m = off / C_, k = off % C_;
        size_t o = ((size_t)(m>>7)*16 + (k>>5))*TILEA_H
                 + (size_t)(m & 127)*A_PAD + (k & 31);
        drT[o] = __float2half_rn(wr[off]);
    } else {
        int j = i - (RW0+RW1+RW2+RW3+RW4);
        int b = j / (C_*N_);
        int rem = j - b*(C_*N_);
        int c = rem >> 12, pos = rem & 4095;
        size_t o = (size_t)b*BMN_B + ((size_t)(pos>>7)*16 + (c>>5))*TILEB_H
                 + (size_t)(c & 31)*B_PAD_T + (pos & 127);
        dx[o] = __float2half_rn(x[j]);
    }
}

// ---------------------------------------------------------------------------
// combined bias: rows 2c -> bqkv; rows 2c+1 -> bm + Wm@bv; v rows -> bqkv[1024+]
__global__ void bias_comb(const float* __restrict__ bqkv,
                          const float* __restrict__ bm,
                          const float* __restrict__ Wm,
                          float* __restrict__ outb)
{
    __shared__ float sm[4];
    int r = blockIdx.x, tid = threadIdx.x;
    if (r < 2048){
        int reg = r >> 10;
        int c = (r - reg*1024) >> 1;
        int cc = reg*512 + c;
        if ((r & 1) == 0){
            if (tid == 0) outb[r] = bqkv[cc];
        } else {
            const float* wrow = Wm + (size_t)cc*C_;
            float s = 0.f;
            for (int i = tid; i < C_; i += 128)
                s += wrow[i] * bqkv[1024 + i];
            #pragma unroll
            for (int o = 16; o; o >>= 1)
                s += __shfl_xor_sync(0xffffffffu, s, o);
            if ((tid & 31) == 0) sm[tid >> 5] = s;
            __syncthreads();
            if (tid == 0) outb[r] = bm[cc] + sm[0]+sm[1]+sm[2]+sm[3];
        }
    } else {
        if (tid == 0) outb[r] = bqkv[1024 + r - 2048];
    }
}

// ---------------------------------------------------------------------------
__global__ void softmax_q(const __half* __restrict__ sq, __half* __restrict__ qh)
{
    __shared__ float red[8];
    __shared__ float bc;
    const int row = blockIdx.x;
    const int b = row >> 9, c = row & 511;
    const size_t tb = (size_t)b*AFMT_BIG + (size_t)(c>>7)*128*TILEA_H
                    + (size_t)(c & 127)*A_PAD;

    float v[16];
    float mx = -1e30f;
    #pragma unroll
    for (int i = 0; i < 2; i++){
        int u = threadIdx.x + (i << 8);
        size_t off = tb + (size_t)(u >> 2)*TILEA_H + (u & 3)*8;
        uint4 w = *(const uint4*)(sq + off);
        float2 f0 = unpack_h2(w.x), f1 = unpack_h2(w.y);
        float2 f2 = unpack_h2(w.z), f3 = unpack_h2(w.w);
        v[i*8+0]=f0.x; v[i*8+1]=f0.y; v[i*8+2]=f1.x; v[i*8+3]=f1.y;
        v[i*8+4]=f2.x; v[i*8+5]=f2.y; v[i*8+6]=f3.x; v[i*8+7]=f3.y;
        mx = fmaxf(mx, fmaxf(fmaxf(fmaxf(f0.x,f0.y),fmaxf(f1.x,f1.y)),
                             fmaxf(fmaxf(f2.x,f2.y),fmaxf(f3.x,f3.y))));
    }
    #pragma unroll
    for (int off = 16; off; off >>= 1)
        mx = fmaxf(mx, __shfl_xor_sync(0xffffffffu, mx, off));
    if ((threadIdx.x & 31) == 0) red[threadIdx.x >> 5] = mx;
    __syncthreads();
    if (threadIdx.x == 0){
        float tv = red[0];
        #pragma unroll
        for (int i = 1; i < 8; i++) tv = fmaxf(tv, red[i]);
        bc = tv;
    }
    __syncthreads();
    mx = bc;

    float sm = 0.f;
    #pragma unroll
    for (int i = 0; i < 16; i++){
        v[i] = __expf(v[i] - mx);
        sm += v[i];
    }
    #pragma unroll
    for (int off = 16; off; off >>= 1)
        sm += __shfl_xor_sync(0xffffffffu, sm, off);
    __syncthreads();
    if ((threadIdx.x & 31) == 0) red[threadIdx.x >> 5] = sm;
    __syncthreads();
    if (threadIdx.x == 0){
        float tv = 0.f;
        #pragma unroll
        for (int i = 0; i < 8; i++) tv += red[i];
        bc = tv;
    }
    __syncthreads();
    const float rinv = 1.f / bc;
    #pragma unroll
    for (int i = 0; i < 2; i++){
        int u = threadIdx.x + (i << 8);
        size_t off = tb + (size_t)(u >> 2)*TILEA_H + (u & 3)*8;
        uint4 w;
        w.x = pack_h2(v[i*8+0]*rinv, v[i*8+1]*rinv);
        w.y = pack_h2(v[i*8+2]*rinv, v[i*8+3]*rinv);
        w.z = pack_h2(v[i*8+4]*rinv, v[i*8+5]*rinv);
        w.w = pack_h2(v[i*8+6]*rinv, v[i*8+7]*rinv);
        *(uint4*)(qh + off) = w;
    }
}

// ---------------------------------------------------------------------------
__global__ void softmax_attn(float* __restrict__ S, __half* __restrict__ at)
{
    __shared__ float red[4];
    __shared__ float bc;
    const int row = blockIdx.x;
    const int b = row >> 9, c = row & 511;
    float* p = S + (size_t)row * 512;
    const size_t tb = (size_t)b*AFMT_AT + (size_t)(c>>7)*16*TILEA_H
                    + (size_t)(c & 127)*A_PAD;

    float v[4];
    float mx = -1e30f;
    #pragma unroll
    for (int i = 0; i < 4; i++){
        int idx = threadIdx.x + (i << 7);
        v[i] = p[idx];
        mx = fmaxf(mx, v[i]);
    }
    #pragma unroll
    for (int off = 16; off; off >>= 1)
        mx = fmaxf(mx, __shfl_xor_sync(0xffffffffu, mx, off));
    if ((threadIdx.x & 31) == 0) red[threadIdx.x >> 5] = mx;
    __syncthreads();
    if (threadIdx.x == 0)
        bc = fmaxf(fmaxf(red[0], red[1]), fmaxf(red[2], red[3]));
    __syncthreads();
    mx = bc;

    float sm = 0.f;
    #pragma unroll
    for (int i = 0; i < 4; i++){
        v[i] = __expf(v[i] - mx);
        sm += v[i];
    }
    #pragma unroll
    for (int off = 16; off; off >>= 1)
        sm += __shfl_xor_sync(0xffffffffu, sm, off);
    __syncthreads();
    if ((threadIdx.x & 31) == 0) red[threadIdx.x >> 5] = sm;
    __syncthreads();
    if (threadIdx.x == 0) bc = red[0] + red[1] + red[2] + red[3];
    __syncthreads();
    const float rinv = 1.f / bc;
    #pragma unroll
    for (int i = 0; i < 4; i++){
        int d = threadIdx.x + (i << 7);
        float f = v[i] * rinv;
        p[d] = f;
        at[tb + (size_t)(d>>5)*TILEA_H + (d & 31)] = __float2half_rn(f);
    }
}

// ---------------------------------------------------------------------------
extern "C" void kernel_launch(void* const* d_in, const int* in_sizes, int n_in,
                              void* d_out, int out_size)
{
    const float* x    = (const float*)d_in[0];
    const float* Wqkv = (const float*)d_in[1];
    const float* bqkv = (const float*)d_in[2];
    const float* Wm   = (const float*)d_in[3];
    const float* bm   = (const float*)d_in[4];
    const float* Wg   = (const float*)d_in[5];
    const float* bg   = (const float*)d_in[6];
    const float* Wr   = (const float*)d_in[7];
    const float* br   = (const float*)d_in[8];

    float* out  = (float*)d_out;
    float* attn = out + (size_t)B_ * C_ * N_;

    cudaFuncSetAttribute(mma_gemm, cudaFuncAttributeMaxDynamicSharedMemorySize, SMEM_TOTAL);

    __half *vhT, *xhT, *yhT, *sq, *kh, *qh, *at, *gph;
    __half *wcomb, *wmA, *wvT, *wgT, *wrT;
    float  *bcomb;
    cudaGetSymbolAddress((void**)&vhT,  g_vhT);
    cudaGetSymbolAddress((void**)&xhT,  g_xhT);
    cudaGetSymbolAddress((void**)&yhT,  g_yhT);
    cudaGetSymbolAddress((void**)&sq,   g_sq);
    cudaGetSymbolAddress((void**)&kh,   g_kh);
    cudaGetSymbolAddress((void**)&qh,   g_qh);
    cudaGetSymbolAddress((void**)&at,   g_at);
    cudaGetSymbolAddress((void**)&gph,  g_gph);
    cudaGetSymbolAddress((void**)&wcomb, g_wcomb);
    cudaGetSymbolAddress((void**)&wmA,   g_wmA);
    cudaGetSymbolAddress((void**)&wvT,   g_wvT);
    cudaGetSymbolAddress((void**)&wgT,   g_wgT);
    cudaGetSymbolAddress((void**)&wrT,   g_wrT);
    cudaGetSymbolAddress((void**)&bcomb, g_bcomb);

    // 0) retile + combined bias
    retile_all<<<(RT_TOTAL + 255)/256, 256>>>(
        Wqkv, wcomb, Wm, wmA, wvT, Wg, wgT, Wr, wrT, x, xhT);
    bias_comb<<<2560, 128>>>(bqkv, bm, Wm, bcomb);

    // 1) W' = Wm @ Wv -> combined odd rows (mode 6; N=512, batch 1)
    mma_gemm<<<dim3(4, 8, 1), NTHREADS, SMEM_TOTAL>>>(
        wmA, 16, 0,
        wvT, 16, 0, nullptr, 0, 0, 16,
        nullptr, 1.f, nullptr, wcomb, nullptr, nullptr, nullptr,
        16, 1, 6);

    // 2) merged qkv+mqk (mode 7): sq/kh pairs + v tiles
    mma_gemm<<<dim3(32, 20, B_), NTHREADS, SMEM_TOTAL>>>(
        wcomb, 16, 0,
        xhT, 16, BMN_B, nullptr, 0, 0, 16,
        bcomb, 1.f, (float*)vhT, sq, kh, nullptr, nullptr,
        16, 1, 7);

    // 3) softmax_q
    softmax_q<<<NROWS, 256>>>(sq, qh);

    // 4) scores (mode 0, NT, K=4096)
    mma_gemm<<<dim3(4, 4, B_), NTHREADS, SMEM_TOTAL>>>(
        qh, 128, AFMT_BIG,
        kh, 128, AFMT_BIG, nullptr, 0, 0, 128,
        nullptr, 1.0f/sqrtf((float)C_), attn, nullptr, nullptr, nullptr, nullptr,
        128, 0, 0);

    // 5) softmax_attn
    softmax_attn<<<NROWS, 128>>>(attn, at);

    // 6) y (mode 4)
    mma_gemm<<<dim3(32, 4, B_), NTHREADS, SMEM_TOTAL>>>(
        at, 16, AFMT_AT,
        vhT, 16, BMN_B, nullptr, 0, 0, 16,
        nullptr, 1.f, nullptr, yhT, nullptr, nullptr, nullptr,
        16, 1, 4);

    // 7) gate (mode 5)
    mma_gemm<<<dim3(32, 4, B_), NTHREADS, SMEM_TOTAL>>>(
        wgT, 32, 0,
        yhT, 16, BMN_B, xhT, 16, BMN_B, 16,
        bg, 1.f, nullptr, gph, nullptr, nullptr, nullptr,
        32, 1, 5);

    // 8) r + final fuse (mode 1)
    mma_gemm<<<dim3(32, 4, B_), NTHREADS, SMEM_TOTAL>>>(
        wrT, 16, 0,
        xhT, 16, BMN_B, nullptr, 0, 0, 16,
        br, 1.f, out, nullptr, nullptr, gph, yhT,
        16, 1, 1);
}